// round 9
// baseline (speedup 1.0000x reference)
#include <cuda_runtime.h>
#include <cuda_bf16.h>
#include <cstdint>

// CTC batch cost, B=512 T=512 C=128 L=32, S=65, blank=127.
// Probability-domain forward recursion, per-lane power-of-two exponent frames
// (renorm every 32 steps). 1 recursion warp per CTA (spread across SMSPs via
// (b/148)&3), 3 loader warps feeding a 5-stage cp.async.cg ring (TC=16 rows
// per stage). Steady state keeps 4 chunks in flight with wait_group<3>, so a
// straggling sector has ~3 chunk periods of slack before it can stall the
// serial alpha chain.

namespace {
constexpr int Bsz = 512;
constexpr int Tsz = 512;
constexpr int Csz = 128;
constexpr int Lsz = 32;
constexpr int TC   = 16;            // timesteps per stage
constexpr int NCH  = Tsz / TC;      // 32 chunks
constexpr int NST  = 5;             // ring stages (40 KB)
constexpr int F4PC = TC * (Csz / 4);      // 512 float4 per stage
constexpr int STBY = F4PC * 16;           // 8192 bytes per stage
constexpr float LN2F = 0.69314718055994530942f;
constexpr float EPSF = 1e-7f;
}

__device__ __forceinline__ float ex2f_(float x) {
    float r; asm("ex2.approx.ftz.f32 %0, %1;" : "=f"(r) : "f"(x)); return r;
}
__device__ __forceinline__ float lg2f_(float x) {
    float r; asm("lg2.approx.ftz.f32 %0, %1;" : "=f"(r) : "f"(x)); return r;
}
__device__ __forceinline__ void cpasync16(uint32_t dst, const float4* src) {
    asm volatile("cp.async.cg.shared.global [%0], [%1], 16;" :: "r"(dst), "l"(src));
}
__device__ __forceinline__ void cpcommit() {
    asm volatile("cp.async.commit_group;");
}
template <int N> __device__ __forceinline__ void cpwait() {
    asm volatile("cp.async.wait_group %0;" :: "n"(N));
}

__global__ __launch_bounds__(128, 4)
void ctc_loss_kernel(const int* __restrict__ y_true,
                     const float* __restrict__ y_pred,
                     float* __restrict__ out)
{
    __shared__ float4 raw4[NST][F4PC];   // 40 KB ring
    __shared__ int    lab[Lsz];

    const int b    = blockIdx.x;
    const int tid  = threadIdx.x;
    const int wid  = tid >> 5;
    const int lane = tid & 31;
    const int rw   = (b / 148) & 3;     // co-resident CTAs -> different SMSPs

    if (tid < Lsz) lab[tid] = y_true[b * Lsz + tid];

    const bool isComp = (wid == rw);
    int lrank = 0;
    if (!isComp) lrank = ((wid > rw) ? wid - 1 : wid) * 32 + lane;  // 0..95

    const uint32_t rawBase = (uint32_t)__cvta_generic_to_shared(&raw4[0][0]);
    const float4*  src0    = (const float4*)(y_pred + (long)b * Tsz * Csz);

    auto issueChunk = [&](int c) {
        const float4* src = src0 + c * F4PC;
        uint32_t dst = rawBase + (uint32_t)(c % NST) * STBY;
        #pragma unroll
        for (int i = lrank; i < F4PC; i += 96) cpasync16(dst + i * 16, src + i);
        cpcommit();
    };

    // prologue: stages 0..3 in flight; stage 0 complete before compute starts
    if (!isComp) {
        issueChunk(0); issueChunk(1); issueChunk(2); issueChunk(3);
        cpwait<3>();
    }
    __syncthreads();

    // recursion state (probability domain, per-lane frames)
    float a0 = 0.0f, a1 = 0.0f, a2 = 0.0f;
    float skipM = 0.0f, scaleRot = 1.0f, skipRotM = 0.0f;
    int   myLab = 0, laneSrc = 0, shift = 0;
    if (isComp) {
        myLab    = lab[lane];
        skipM    = (lane >= 1 && myLab != lab[lane - 1]) ? 1.0f : 0.0f;
        skipRotM = skipM;
        laneSrc  = (lane + 31) & 31;   // rotate: lane l <- lane (l-1)%32
    }

    for (int c = 0; c < NCH; ++c) {
        if (isComp) {
            const float* rawf = (const float*)&raw4[c % NST][0];
            int t0 = 0;
            if (c == 0) {
                float pb = rawf[Csz - 1] + EPSF;
                float pl = rawf[myLab]   + EPSF;
                a0 = (lane == 0) ? pb : 0.0f;
                a1 = (lane == 0) ? pl : 0.0f;
                t0 = 1;
            }
            #pragma unroll
            for (int tt = t0; tt < TC; ++tt) {
                const float* row = rawf + tt * Csz;
                float pb = row[Csz - 1] + EPSF;   // blank prob (broadcast LDS)
                float pl = row[myLab]   + EPSF;   // label prob (scattered LDS)

                float raw = __shfl_sync(0xffffffffu, a1, laneSrc);
                float tsum = a1 + a0;

                // odd slot: a1 = (a1 + a0 + skip*alpha[2l-1]) * pl
                // (skipRotM = skipM * scaleRot, exact power-of-two folding)
                a1 = __fmaf_rn(raw, skipRotM, tsum) * pl;

                // even slot: lanes>=1 update a0; lane 0 updates a2 (s=64)
                float rot = raw * scaleRot;
                float x   = (lane == 0) ? a2 : a0;
                float r0  = (x + rot) * pb;
                if (lane == 0) { a2 = r0; a0 = a0 * pb; }
                else           { a0 = r0; }
            }

            if (c & 1) {
                // per-lane renorm + frame exchange (every 32 steps)
                float m = fmaxf(fmaxf(a0, a1), a2);   // a2==0 on lanes != 0
                int e = 0;
                if (m > 0.0f) e = (int)(__float_as_uint(m) >> 23) - 127;
                if (e > 126) e = 126;
                float sc = __uint_as_float((unsigned)(127 - e) << 23); // 2^-e
                a0 *= sc; a1 *= sc; a2 *= sc;
                shift += e;

                int shSrc = __shfl_sync(0xffffffffu, shift, laneSrc);
                if (m == 0.0f) shift = shSrc;       // dead lane adopts frame
                int d = shSrc - shift;
                d = (d > 126) ? 126 : d;
                scaleRot = (d < -126) ? 0.0f
                         : __uint_as_float((unsigned)(127 + d) << 23);  // 2^d
                skipRotM = skipM * scaleRot;
            }
        } else {
            if (c + 4 < NCH)      { issueChunk(c + 4); cpwait<3>(); }
            else if (c + 3 < NCH) { cpwait<2>(); }
            else if (c + 2 < NCH) { cpwait<1>(); }
            else if (c + 1 < NCH) { cpwait<0>(); }
        }
        __syncthreads();
    }

    if (isComp) {
        // log2 of alpha_T[S-1] (lane 0: a2) and alpha_T[S-2] (lane 31: a1)
        float v  = lg2f_((lane == 31) ? a1 : a2) + (float)shift;
        float v1 = __shfl_sync(0xffffffffu, v, 31);
        if (lane == 0) {
            float mm = fmaxf(v, v1);
            float dd = fabsf(v - v1);
            out[b] = -LN2F * (mm + lg2f_(1.0f + ex2f_(-dd)));
        }
    }
}

extern "C" void kernel_launch(void* const* d_in, const int* in_sizes, int n_in,
                              void* d_out, int out_size)
{
    const int*   y_true = (const int*)d_in[0];    // [512, 32] int32
    const float* y_pred = (const float*)d_in[1];  // [512, 512, 128] float32
    float*       out    = (float*)d_out;          // [512, 1] float32
    (void)in_sizes; (void)n_in; (void)out_size;

    ctc_loss_kernel<<<Bsz, 128>>>(y_true, y_pred, out);
}